// round 8
// baseline (speedup 1.0000x reference)
#include <cuda_runtime.h>
#include <cuda_fp16.h>
#include <cuda_bf16.h>
#include <cstdint>

#define NN 100000
#define NE 1600000
#define TOT (NE + NN)
#define HD 128

union H2U { unsigned int u; __half2 h; };
__device__ __forceinline__ unsigned int h2_to_u(__half2 h) { H2U c; c.h = h; return c.u; }
__device__ __forceinline__ __half2 u_to_h2(unsigned int u) { H2U c; c.u = u; return c.h; }

__device__ __forceinline__ unsigned int pack_bf16(float lo, float hi) {
    unsigned r;
    asm("cvt.rn.bf16x2.f32 %0, %1, %2;" : "=r"(r) : "f"(hi), "f"(lo));
    return r;
}

// ---------------- scratch (device globals; no allocation allowed) ------------
__device__ float4 g_hF[NN * 32];     // fp32 final h (input to GEMM2)
__device__ uint4  g_h0h[NN * 16];    // fp16 h0 (alpha term)
__device__ uint4  g_h16a[NN * 16];   // fp16 ping
__device__ uint4  g_h16b[NN * 16];   // fp16 pong
__device__ int    g_cnt[NN];
__device__ int    g_fill[NN];
__device__ float  g_dinv[NN];
__device__ int    g_rowptr[NN + 1];
__device__ int2   g_ew[TOT];         // .x = src col, .y = float bits of 0.9*w
__device__ int    g_bsum[64];
__device__ int    g_is64;

// ---------------- init counters + edge dtype detection -----------------------
__global__ void initdet(const int* ei32) {
    int n = blockIdx.x * blockDim.x + threadIdx.x;
    if (n < NN) { g_cnt[n] = 1; g_fill[n] = 0; }
    if (blockIdx.x == 0 && threadIdx.x < 32) {
        int lane = threadIdx.x;
        int orv = 0;
        for (int i = lane; i < 1024; i += 32) orv |= ei32[2 * i + 1];
        #pragma unroll
        for (int off = 16; off; off >>= 1) orv |= __shfl_xor_sync(0xFFFFFFFFu, orv, off);
        if (lane == 0) g_is64 = (orv == 0) ? 1 : 0;
    }
}

__device__ __forceinline__ int edge_src(const void* ei, int e) {
    if (g_is64) return (int)((const long long*)ei)[e];
    return ((const int*)ei)[e];
}
__device__ __forceinline__ int edge_dst(const void* ei, int e) {
    if (g_is64) return (int)((const long long*)ei)[NE + e];
    return ((const int*)ei)[NE + e];
}

__global__ void hist(const void* __restrict__ ei) {
    int e = blockIdx.x * blockDim.x + threadIdx.x;
    if (e < NE) atomicAdd(&g_cnt[edge_dst(ei, e)], 1);
}

__global__ void scan1() {
    __shared__ int sh[256];
    int tid = threadIdx.x;
    int base = blockIdx.x * 2048 + tid * 8;
    int v[8];
    int s = 0;
    #pragma unroll
    for (int i = 0; i < 8; i++) {
        int idx = base + i;
        v[i] = (idx < NN) ? g_cnt[idx] : 0;
        if (idx < NN) g_dinv[idx] = rsqrtf((float)v[i]);
        s += v[i];
    }
    sh[tid] = s;
    __syncthreads();
    for (int off = 1; off < 256; off <<= 1) {
        int t = (tid >= off) ? sh[tid - off] : 0;
        __syncthreads();
        sh[tid] += t;
        __syncthreads();
    }
    int run = sh[tid] - s;
    #pragma unroll
    for (int i = 0; i < 8; i++) {
        int idx = base + i;
        if (idx < NN) g_rowptr[idx] = run;
        run += v[i];
    }
    if (tid == 255) g_bsum[blockIdx.x] = sh[255];
}

__global__ void scanfix() {
    __shared__ int soff;
    int idx = blockIdx.x * blockDim.x + threadIdx.x;
    int sblk = (blockIdx.x * 256) >> 11;
    if (threadIdx.x == 0) {
        int a = 0;
        for (int i = 0; i < sblk; i++) a += g_bsum[i];
        soff = a;
    }
    __syncthreads();
    if (idx < NN) g_rowptr[idx] += soff;
    if (idx == 0) g_rowptr[NN] = TOT;
}

__global__ void scatter(const void* __restrict__ ei) {
    int e = blockIdx.x * blockDim.x + threadIdx.x;
    if (e < NE) {
        int s = edge_src(ei, e);
        int d = edge_dst(ei, e);
        int pos = g_rowptr[d] + atomicAdd(&g_fill[d], 1);
        float ww = 0.9f * g_dinv[s] * g_dinv[d];
        g_ew[pos] = make_int2(s, __float_as_int(ww));
    } else if (e < TOT) {
        int n = e - NE;
        int pos = g_rowptr[n] + atomicAdd(&g_fill[n], 1);
        float di = g_dinv[n];
        g_ew[pos] = make_int2(n, __float_as_int(0.9f * di * di));
    }
}

// ---------------- HMMA GEMM: D = X @ W + b (fp32 via 3-term bf16 split) ------
// CTA: 128x128 tile, 8 warps (4m x 2n), warp tile 32x64, mma.m16n8k16.bf16.
// Smem: A_hi/A_lo [128][136] bf16 (row,k); B_hi/B_lo [128][136] bf16 (n,k).
#define LDK 136
#define SM_A_HI 0
#define SM_A_LO (SM_A_HI + 128 * LDK * 2)
#define SM_B_HI (SM_A_LO + 128 * LDK * 2)
#define SM_B_LO (SM_B_HI + 128 * LDK * 2)
#define SM_BIAS (SM_B_LO + 128 * LDK * 2)
#define SM_GEMM_TOTAL (SM_BIAS + 512)

__device__ __forceinline__ void mma16816(float* d, unsigned a0, unsigned a1,
                                         unsigned a2, unsigned a3,
                                         unsigned b0, unsigned b1) {
    asm volatile("mma.sync.aligned.m16n8k16.row.col.f32.bf16.bf16.f32 "
                 "{%0,%1,%2,%3}, {%4,%5,%6,%7}, {%8,%9}, {%0,%1,%2,%3};"
                 : "+f"(d[0]), "+f"(d[1]), "+f"(d[2]), "+f"(d[3])
                 : "r"(a0), "r"(a1), "r"(a2), "r"(a3), "r"(b0), "r"(b1));
}

__global__ __launch_bounds__(256) void gemm_mma(
    const float* __restrict__ X, const float* __restrict__ Wm,
    const float* __restrict__ bias, float* __restrict__ out, int mode)
{
    extern __shared__ char smem[];
    __nv_bfloat16* Ah = (__nv_bfloat16*)(smem + SM_A_HI);
    __nv_bfloat16* Al = (__nv_bfloat16*)(smem + SM_A_LO);
    __nv_bfloat16* Bh = (__nv_bfloat16*)(smem + SM_B_HI);
    __nv_bfloat16* Bl = (__nv_bfloat16*)(smem + SM_B_LO);
    float* sb = (float*)(smem + SM_BIAS);

    int tid = threadIdx.x;
    int wid = tid >> 5;
    int lane = tid & 31;
    int rowBase = blockIdx.x * 128;

    if (tid < 128) sb[tid] = bias[tid];

    // load + split A rows (bf16 hi/lo), [row][k] padded LDK
    for (int i = tid; i < 4096; i += 256) {
        int r = i >> 5;
        int kq = i & 31;
        float4 v = make_float4(0.f, 0.f, 0.f, 0.f);
        if (rowBase + r < NN) v = reinterpret_cast<const float4*>(X)[(rowBase + r) * 32 + kq];
        float f[4] = {v.x, v.y, v.z, v.w};
        float hf[4], lf[4];
        #pragma unroll
        for (int c = 0; c < 4; c++) {
            hf[c] = __bfloat162float(__float2bfloat16_rn(f[c]));
            lf[c] = f[c] - hf[c];
        }
        int o = r * LDK + kq * 4;
        *(uint2*)&Ah[o] = make_uint2(pack_bf16(hf[0], hf[1]), pack_bf16(hf[2], hf[3]));
        *(uint2*)&Al[o] = make_uint2(pack_bf16(lf[0], lf[1]), pack_bf16(lf[2], lf[3]));
    }
    // load + split + transpose W: Wm[k][n] -> B[n][k]
    for (int i = tid; i < 4096; i += 256) {
        int k = i >> 5;
        int nq = i & 31;
        float4 v = reinterpret_cast<const float4*>(Wm)[k * 32 + nq];
        float f[4] = {v.x, v.y, v.z, v.w};
        #pragma unroll
        for (int c = 0; c < 4; c++) {
            int n = nq * 4 + c;
            __nv_bfloat16 hb = __float2bfloat16_rn(f[c]);
            Bh[n * LDK + k] = hb;
            Bl[n * LDK + k] = __float2bfloat16_rn(f[c] - __bfloat162float(hb));
        }
    }
    __syncthreads();

    int wm = wid & 3;          // 0..3 -> rows wm*32
    int wn = wid >> 2;         // 0..1 -> cols wn*64
    int qr = lane >> 2;        // 0..7
    int qc = (lane & 3) * 2;   // 0,2,4,6

    float acc[2][8][4];
    #pragma unroll
    for (int mt = 0; mt < 2; mt++)
        #pragma unroll
        for (int nt = 0; nt < 8; nt++)
            #pragma unroll
            for (int c = 0; c < 4; c++) acc[mt][nt][c] = 0.f;

    const __nv_bfloat16* APT[3] = {Ah, Al, Ah};
    const __nv_bfloat16* BPT[3] = {Bh, Bh, Bl};

    #pragma unroll
    for (int term = 0; term < 3; term++) {
        const __nv_bfloat16* A = APT[term];
        const __nv_bfloat16* B = BPT[term];
        #pragma unroll
        for (int ks = 0; ks < 8; ks++) {
            int k0 = ks * 16;
            unsigned a[2][4], b[8][2];
            #pragma unroll
            for (int mt = 0; mt < 2; mt++) {
                int r = wm * 32 + mt * 16 + qr;
                const __nv_bfloat16* ap = A + r * LDK + k0 + qc;
                a[mt][0] = *(const unsigned*)(ap);
                a[mt][1] = *(const unsigned*)(ap + 8 * LDK);
                a[mt][2] = *(const unsigned*)(ap + 8);
                a[mt][3] = *(const unsigned*)(ap + 8 * LDK + 8);
            }
            #pragma unroll
            for (int nt = 0; nt < 8; nt++) {
                int n = wn * 64 + nt * 8 + qr;
                const __nv_bfloat16* bp = B + n * LDK + k0 + qc;
                b[nt][0] = *(const unsigned*)(bp);
                b[nt][1] = *(const unsigned*)(bp + 8);
            }
            #pragma unroll
            for (int mt = 0; mt < 2; mt++)
                #pragma unroll
                for (int nt = 0; nt < 8; nt++)
                    mma16816(acc[mt][nt], a[mt][0], a[mt][1], a[mt][2], a[mt][3],
                             b[nt][0], b[nt][1]);
        }
    }

    // epilogue
    #pragma unroll
    for (int mt = 0; mt < 2; mt++) {
        #pragma unroll
        for (int nt = 0; nt < 8; nt++) {
            int c = wn * 64 + nt * 8 + qc;
            float bx = sb[c], by = sb[c + 1];
            int r0 = rowBase + wm * 32 + mt * 16 + qr;
            int r1 = r0 + 8;
            float d0 = acc[mt][nt][0] + bx, d1 = acc[mt][nt][1] + by;
            float d2 = acc[mt][nt][2] + bx, d3 = acc[mt][nt][3] + by;
            if (mode) {
                d0 = fmaxf(d0, 0.f); d1 = fmaxf(d1, 0.f);
                d2 = fmaxf(d2, 0.f); d3 = fmaxf(d3, 0.f);
                unsigned p0 = h2_to_u(__floats2half2_rn(d0, d1));
                unsigned p1 = h2_to_u(__floats2half2_rn(d2, d3));
                if (r0 < NN) {
                    ((unsigned*)g_h16a)[r0 * 64 + c / 2] = p0;
                    ((unsigned*)g_h0h)[r0 * 64 + c / 2] = p0;
                }
                if (r1 < NN) {
                    ((unsigned*)g_h16b)[0] = ((unsigned*)g_h16b)[0];  // no-op keep
                    ((unsigned*)g_h16a)[r1 * 64 + c / 2] = p1;
                    ((unsigned*)g_h0h)[r1 * 64 + c / 2] = p1;
                }
            } else {
                if (r0 < NN) *(float2*)(out + r0 * HD + c) = make_float2(d0, d1);
                if (r1 < NN) *(float2*)(out + r1 * HD + c) = make_float2(d2, d3);
            }
        }
    }
}

// ---------------- APPNP propagation: 16 threads/node, uint4 fp16 gathers -----
__global__ __launch_bounds__(256) void propagate(int t) {
    int idx = blockIdx.x * blockDim.x + threadIdx.x;
    int node = idx >> 4;
    int lane = idx & 15;
    if (node >= NN) return;

    const uint4* __restrict__ hin = (t & 1) ? g_h16b : g_h16a;
    uint4* __restrict__ hout      = (t & 1) ? g_h16a : g_h16b;

    int beg = g_rowptr[node];
    int end = g_rowptr[node + 1];

    float a0 = 0.f, a1 = 0.f, a2 = 0.f, a3 = 0.f;
    float a4 = 0.f, a5 = 0.f, a6 = 0.f, a7 = 0.f;
    #pragma unroll 4
    for (int e = beg; e < end; e++) {
        int2 ew = __ldg(&g_ew[e]);
        float ww = __int_as_float(ew.y);
        uint4 hv = __ldg(&hin[ew.x * 16 + lane]);
        float2 f0 = __half22float2(u_to_h2(hv.x));
        float2 f1 = __half22float2(u_to_h2(hv.y));
        float2 f2 = __half22float2(u_to_h2(hv.z));
        float2 f3 = __half22float2(u_to_h2(hv.w));
        a0 = fmaf(ww, f0.x, a0); a1 = fmaf(ww, f0.y, a1);
        a2 = fmaf(ww, f1.x, a2); a3 = fmaf(ww, f1.y, a3);
        a4 = fmaf(ww, f2.x, a4); a5 = fmaf(ww, f2.y, a5);
        a6 = fmaf(ww, f3.x, a6); a7 = fmaf(ww, f3.y, a7);
    }

    uint4 zv = __ldg(&g_h0h[node * 16 + lane]);
    float2 z0 = __half22float2(u_to_h2(zv.x));
    float2 z1 = __half22float2(u_to_h2(zv.y));
    float2 z2 = __half22float2(u_to_h2(zv.z));
    float2 z3 = __half22float2(u_to_h2(zv.w));
    float o0 = a0 + 0.1f * z0.x, o1 = a1 + 0.1f * z0.y;
    float o2 = a2 + 0.1f * z1.x, o3 = a3 + 0.1f * z1.y;
    float o4 = a4 + 0.1f * z2.x, o5 = a5 + 0.1f * z2.y;
    float o6 = a6 + 0.1f * z3.x, o7 = a7 + 0.1f * z3.y;

    if (t == 9) {
        g_hF[node * 32 + lane * 2 + 0] = make_float4(o0, o1, o2, o3);
        g_hF[node * 32 + lane * 2 + 1] = make_float4(o4, o5, o6, o7);
    } else {
        uint4 u;
        u.x = h2_to_u(__floats2half2_rn(o0, o1));
        u.y = h2_to_u(__floats2half2_rn(o2, o3));
        u.z = h2_to_u(__floats2half2_rn(o4, o5));
        u.w = h2_to_u(__floats2half2_rn(o6, o7));
        hout[node * 16 + lane] = u;
    }
}

// ---------------- launch ------------------------------------------------------
extern "C" void kernel_launch(void* const* d_in, const int* in_sizes, int n_in,
                              void* d_out, int out_size) {
    const float* x  = (const float*)d_in[0];
    const void*  ei = d_in[1];
    const float* W1 = (const float*)d_in[2];
    const float* b1 = (const float*)d_in[3];
    const float* W2 = (const float*)d_in[4];
    const float* b2 = (const float*)d_in[5];
    float* out = (float*)d_out;

    void* p_hF = nullptr;
    cudaGetSymbolAddress(&p_hF, g_hF);

    cudaFuncSetAttribute(gemm_mma, cudaFuncAttributeMaxDynamicSharedMemorySize, SM_GEMM_TOTAL);

    const int T = 256;
    initdet<<<(NN + T - 1) / T, T>>>((const int*)ei);
    hist<<<(NE + T - 1) / T, T>>>(ei);
    scan1<<<(NN + 2047) / 2048, 256>>>();
    scanfix<<<(NN + T - 1) / T, T>>>();
    scatter<<<(TOT + T - 1) / T, T>>>(ei);

    gemm_mma<<<(NN + 127) / 128, 256, SM_GEMM_TOTAL>>>(x, W1, b1, nullptr, 1);

    for (int t = 0; t < 10; t++)
        propagate<<<(NN * 16 + T - 1) / T, T>>>(t);

    gemm_mma<<<(NN + 127) / 128, 256, SM_GEMM_TOTAL>>>((const float*)p_hF, W2, b2, out, 0);
}